// round 12
// baseline (speedup 1.0000x reference)
#include <cuda_runtime.h>
#include <math.h>

#define NB 1024
#define NC 100000
#define THREADS 256

#define F4_TOTAL   25600000          // NB*NC/4
#define F4_PER_ROW 25000             // NC/4
#define NSTREAM    1183              // stream CTAs
#define GRID_TOT   1184              // 148 SMs * 8 CTAs, one perfect wave
#define CHUNK      21641             // ceil(F4_TOTAL/NSTREAM), spans <=2 rows

// scratch (zero-initialized at module load; finalize block resets them)
static __device__ unsigned long long g_sum[NB];   // fixed-point row exp-sums
static __device__ float g_delta[NB];              // e(l_mod)-e(l_orig) per row
static __device__ float g_lmod[NB];               // modified target logit
static __device__ unsigned int g_done;

__device__ __forceinline__ float ex2_fast(float x) {
    float y;
    asm("ex2.approx.ftz.f32 %0, %1;" : "=f"(y) : "f"(x));
    return y;
}

// 64 * log2(e)
#define K2 92.33248261625200f
#define LOG2E 1.4426950408889634f
#define FXSCALE 1099511627776.0f     // 2^40
#define FXINV   (1.0 / 1099511627776.0)

__device__ __forceinline__ float term(float v) {
    float c = fminf(fmaxf(v, -1.0f), 1.0f);
    return ex2_fast(fmaf(c, K2, -K2));   // exp(64*c - 64)
}

__device__ __forceinline__ unsigned int ld_acq(const unsigned int* p) {
    unsigned int v;
    asm volatile("ld.acquire.gpu.global.u32 %0, [%1];" : "=r"(v) : "l"(p) : "memory");
    return v;
}

__global__ void __launch_bounds__(THREADS)
fused_loss_kernel(const float* __restrict__ x,
                  const int* __restrict__ label,
                  const float* __restrict__ margin,
                  float* __restrict__ out) {
    const int lane = threadIdx.x & 31;
    const int wid  = threadIdx.x >> 5;
    __shared__ float red[THREADS / 32];
    __shared__ float red2[THREADS / 32];

    // ---- block 0: concurrent per-row fixup precompute, then wait+finalize --
    if (blockIdx.x == 0) {
        #pragma unroll
        for (int k = 0; k < NB / THREADS; k++) {          // 4 rows per thread
            const int r = threadIdx.x + k * THREADS;
            int lb = __ldg(label + r);
            const bool valid = (lb >= 0);
            int tgt = valid ? lb : 0;
            tgt = min(max(tgt, 0), NC - 1);
            const float mg = valid ? __ldg(margin + r) : 0.0f;

            float xt = __ldg(x + (size_t)r * NC + tgt);
            float c  = fminf(fmaxf(xt, -1.0f), 1.0f);
            float l_mod = 64.0f * cosf(acosf(c) + mg);

            g_lmod[r]  = l_mod;
            g_delta[r] = ex2_fast((l_mod - 64.0f) * LOG2E)
                       - ex2_fast(fmaf(c, K2, -K2));
        }
        __syncthreads();

        if (threadIdx.x == 0) {
            while (ld_acq(&g_done) != (unsigned int)NSTREAM) __nanosleep(256);
        }
        __syncthreads();

        // combine: nll[r] = 64 + log(sum + delta) - l_mod ; mean over rows
        float acc = 0.0f;
        #pragma unroll
        for (int k = 0; k < NB / THREADS; k++) {
            const int r = threadIdx.x + k * THREADS;
            float stot = (float)((double)g_sum[r] * FXINV) + g_delta[r];
            acc += 64.0f + logf(stot) - g_lmod[r];
            g_sum[r] = 0ull;                              // reset for replay
        }
        if (threadIdx.x == 0) g_done = 0;

        #pragma unroll
        for (int o = 16; o; o >>= 1) acc += __shfl_xor_sync(0xFFFFFFFFu, acc, o);
        if (lane == 0) red[wid] = acc;
        __syncthreads();
        if (wid == 0) {
            float u = (lane < THREADS / 32) ? red[lane] : 0.0f;
            #pragma unroll
            for (int o = (THREADS / 64); o; o >>= 1)
                u += __shfl_xor_sync(0xFFFFFFFFu, u, o);
            if (lane == 0) out[0] = u * (1.0f / (float)NB);
        }
        return;
    }

    // ---- stream blocks: equal contiguous chunks of the flat array ----------
    const int cid  = blockIdx.x - 1;
    const int base = cid * CHUNK;
    const int end  = min(base + CHUNK, F4_TOTAL);
    const int r0   = base / F4_PER_ROW;                   // first row touched
    const int bnd  = (r0 + 1) * F4_PER_ROW;               // row boundary (f4 idx)

    const float4* __restrict__ p = reinterpret_cast<const float4*>(x);

    float s0 = 0.0f, s1 = 0.0f;
    #pragma unroll 8
    for (int i = base + threadIdx.x; i < end; i += THREADS) {
        float4 v = __ldcs(p + i);
        float t = term(v.x) + term(v.y) + term(v.z) + term(v.w);
        if (i < bnd) s0 += t; else s1 += t;
    }

    // block reduce both accumulators
    #pragma unroll
    for (int o = 16; o; o >>= 1) {
        s0 += __shfl_xor_sync(0xFFFFFFFFu, s0, o);
        s1 += __shfl_xor_sync(0xFFFFFFFFu, s1, o);
    }
    if (lane == 0) { red[wid] = s0; red2[wid] = s1; }
    __syncthreads();

    if (threadIdx.x == 0) {
        float t0 = 0.0f, t1 = 0.0f;
        #pragma unroll
        for (int w = 0; w < THREADS / 32; w++) { t0 += red[w]; t1 += red2[w]; }

        atomicAdd(&g_sum[r0], (unsigned long long)(t0 * FXSCALE));
        if (r0 + 1 < NB && t1 != 0.0f)
            atomicAdd(&g_sum[r0 + 1], (unsigned long long)(t1 * FXSCALE));

        __threadfence();
        atomicAdd(&g_done, 1u);
    }
}

extern "C" void kernel_launch(void* const* d_in, const int* in_sizes, int n_in,
                              void* d_out, int out_size) {
    const float* x      = (const float*)d_in[0];
    const int*   label  = (const int*)d_in[1];
    const float* margin = (const float*)d_in[2];
    float*       out    = (float*)d_out;

    fused_loss_kernel<<<GRID_TOT, THREADS>>>(x, label, margin, out);
}

// round 13
// speedup vs baseline: 1.0316x; 1.0316x over previous
#include <cuda_runtime.h>
#include <math.h>

#define NB 1024
#define NC 100000
#define THREADS 256

// scratch: per-row NLL
static __device__ float g_nll[NB];

__device__ __forceinline__ float ex2_fast(float x) {
    float y;
    asm("ex2.approx.ftz.f32 %0, %1;" : "=f"(y) : "f"(x));
    return y;
}

// 64 * log2(e)
#define K2 92.33248261625200f
#define LOG2E 1.4426950408889634f

__device__ __forceinline__ float term(float v) {
    float c = fminf(fmaxf(v, -1.0f), 1.0f);
    return ex2_fast(fmaf(c, K2, -K2));   // exp(64*c - 64)
}

__global__ void __launch_bounds__(THREADS)
row_lse_kernel(const float* __restrict__ x,
               const int* __restrict__ label,
               const float* __restrict__ margin) {
    const int row = blockIdx.x;
    const float4* __restrict__ p =
        reinterpret_cast<const float4*>(x + (size_t)row * NC);
    const int n4 = NC / 4;  // 25000

    // 4 independent accumulators: breaks the serial FADD chain on s
    float s0 = 0.0f, s1 = 0.0f, s2 = 0.0f, s3 = 0.0f;
    #pragma unroll 8
    for (int i = threadIdx.x; i < n4; i += THREADS) {
        float4 v = __ldcs(p + i);
        s0 += term(v.x);
        s1 += term(v.y);
        s2 += term(v.z);
        s3 += term(v.w);
    }
    float s = (s0 + s1) + (s2 + s3);

    // block reduction
    __shared__ float red[THREADS / 32];
    const int lane = threadIdx.x & 31;
    const int wid  = threadIdx.x >> 5;
    #pragma unroll
    for (int o = 16; o; o >>= 1) s += __shfl_xor_sync(0xFFFFFFFFu, s, o);
    if (lane == 0) red[wid] = s;
    __syncthreads();

    if (wid == 0) {
        float t = (lane < THREADS / 32) ? red[lane] : 0.0f;
        #pragma unroll
        for (int o = (THREADS / 64); o; o >>= 1)
            t += __shfl_xor_sync(0xFFFFFFFFu, t, o);

        if (lane == 0) {
            int lb = __ldg(label + row);
            const bool valid = (lb >= 0);
            int tgt = valid ? lb : 0;
            tgt = min(max(tgt, 0), NC - 1);   // never fabricate OOB address
            const float mg = valid ? __ldg(margin + row) : 0.0f;

            float xt = __ldg(x + (size_t)row * NC + tgt);
            float c  = fminf(fmaxf(xt, -1.0f), 1.0f);
            float l_mod = 64.0f * cosf(acosf(c) + mg);

            // replace target term: subtract original, add modified
            float stot = t - ex2_fast(fmaf(c, K2, -K2))
                           + ex2_fast((l_mod - 64.0f) * LOG2E);

            // nll = lse - l_mod,  lse = 64 + log(stot)
            g_nll[row] = 64.0f + logf(stot) - l_mod;
        }
    }
}

// single-warp mean: 32 threads x 8 float4 = 1024 floats, MLP=8 pipelined
__global__ void __launch_bounds__(32)
mean_kernel(float* __restrict__ out) {
    const int lane = threadIdx.x;
    const float4* __restrict__ p = reinterpret_cast<const float4*>(g_nll);

    float s = 0.0f;
    #pragma unroll
    for (int k = 0; k < 8; k++) {
        float4 v = p[lane + 32 * k];           // 256 float4 total
        s += (v.x + v.y) + (v.z + v.w);
    }
    #pragma unroll
    for (int o = 16; o; o >>= 1) s += __shfl_xor_sync(0xFFFFFFFFu, s, o);
    if (lane == 0) out[0] = s * (1.0f / (float)NB);
}

extern "C" void kernel_launch(void* const* d_in, const int* in_sizes, int n_in,
                              void* d_out, int out_size) {
    const float* x      = (const float*)d_in[0];
    const int*   label  = (const int*)d_in[1];
    const float* margin = (const float*)d_in[2];
    float*       out    = (float*)d_out;

    row_lse_kernel<<<NB, THREADS>>>(x, label, margin);
    mean_kernel<<<1, 32>>>(out);
}